// round 12
// baseline (speedup 1.0000x reference)
#include <cuda_runtime.h>
#include <cuda_fp16.h>
#include <cstdint>

#define Nn 20000
#define Ee 640000
#define Cc 256
#define CAP 160              // bucket capacity per node (deg ~ Poisson(32))

// ---------------- device scratch (no allocations allowed) ----------------
__device__ __half  g_xh [Nn * Cc];    // y0 = dinv*x_norm, half (round-1 gather input)
__device__ __half  g_xbh[Nn * Cc];    // y1 = dinv^2 * S1, half (round-2 gather input)
__device__ float   g_xa [Nn * Cc];    // h2 = dinv * S2, fp32 (GEMM input)
__device__ float   g_dinv[Nn];
__device__ int     g_cnt[Nn];
__device__ float2  g_edge[Nn * CAP];  // bucket CSR: .x = src (bit-cast), .y = raw weight
__device__ int     g_is64;

__device__ __forceinline__ int edge_at(const void* p, long long idx) {
    int v;
    if (g_is64) v = (int)((const long long*)p)[idx];
    else        v = ((const int*)p)[idx];
    return (v < 0) ? 0 : (v >= Nn ? Nn - 1 : v);
}

// ---------------- setup kernels ----------------

__global__ void k_init(const void* ei) {
    int i = blockIdx.x * blockDim.x + threadIdx.x;
    if (i < Nn) g_cnt[i] = 0;
    if (blockIdx.x == 0 && threadIdx.x < 32) {
        const int* p = (const int*)ei;
        int lane = threadIdx.x;
        int nz = 0;
        #pragma unroll
        for (int j = 0; j < 8; j++)
            nz |= p[2 * (lane + 32 * j) + 1];
        unsigned any = __ballot_sync(0xffffffffu, nz != 0);
        if (lane == 0) g_is64 = (any == 0) ? 1 : 0;
    }
}

// SINGLE edge pass: bucket scatter of (src, raw w); cnt atomic only
__global__ void k_edges(const void* __restrict__ ei, const float* __restrict__ w) {
    int e = blockIdx.x * blockDim.x + threadIdx.x;
    if (e < Ee) {
        int r = edge_at(ei, e);
        int c = edge_at(ei, (long long)Ee + e);
        int p = atomicAdd(&g_cnt[c], 1);
        if (p < CAP) g_edge[c * CAP + p] = make_float2(__int_as_float(r), w[e]);
    }
}

// L2-normalize row n of x, deg[n] from bucket weights, scale by dinv, half out
__global__ void k_normalize(const float* __restrict__ x) {
    int n = blockIdx.x;
    int c = threadIdx.x;
    float v = x[n * Cc + c];
    float sq = v * v;
    int cnt = min(g_cnt[n], CAP);
    float wsum = 0.f;
    for (int i = c; i < cnt; i += 256) wsum += g_edge[n * CAP + i].y;
    #pragma unroll
    for (int o = 16; o > 0; o >>= 1) {
        sq   += __shfl_xor_sync(0xffffffffu, sq,   o);
        wsum += __shfl_xor_sync(0xffffffffu, wsum, o);
    }
    __shared__ float ws[8], wd[8];
    __shared__ float s_scale;
    if ((c & 31) == 0) { ws[c >> 5] = sq; wd[c >> 5] = wsum; }
    __syncthreads();
    if (c == 0) {
        float s = 0.f, d = 0.f;
        #pragma unroll
        for (int i = 0; i < 8; i++) { s += ws[i]; d += wd[i]; }
        float dinv = (d > 0.f) ? rsqrtf(d) : 0.f;
        g_dinv[n] = dinv;
        s_scale = dinv / fmaxf(sqrtf(s), 1e-12f);
    }
    __syncthreads();
    g_xh[n * Cc + c] = __float2half_rn(v * s_scale);
}

// ---------------- propagation: 1 warp/node, uint4 loads, f32x2 FMA -------

// accumulate 8 channels (uint4 of halves) * w into 4 packed f32x2 accs
__device__ __forceinline__ void acc8(uint4 v, float w, unsigned long long acc[4]) {
    unsigned long long wp;
    asm("mov.b64 %0, {%1, %1};" : "=l"(wp) : "f"(w));
    float2 f;
    unsigned long long p;
    f = __half22float2(*(__half2*)&v.x);
    asm("mov.b64 %0, {%1, %2};" : "=l"(p) : "f"(f.x), "f"(f.y));
    asm("fma.rn.f32x2 %0, %1, %2, %0;" : "+l"(acc[0]) : "l"(p), "l"(wp));
    f = __half22float2(*(__half2*)&v.y);
    asm("mov.b64 %0, {%1, %2};" : "=l"(p) : "f"(f.x), "f"(f.y));
    asm("fma.rn.f32x2 %0, %1, %2, %0;" : "+l"(acc[1]) : "l"(p), "l"(wp));
    f = __half22float2(*(__half2*)&v.z);
    asm("mov.b64 %0, {%1, %2};" : "=l"(p) : "f"(f.x), "f"(f.y));
    asm("fma.rn.f32x2 %0, %1, %2, %0;" : "+l"(acc[2]) : "l"(p), "l"(wp));
    f = __half22float2(*(__half2*)&v.w);
    asm("mov.b64 %0, {%1, %2};" : "=l"(p) : "f"(f.x), "f"(f.y));
    asm("fma.rn.f32x2 %0, %1, %2, %0;" : "+l"(acc[3]) : "l"(p), "l"(wp));
}

// gather over bucket [beg,end): thread q (0..31) owns channels 8q..8q+7
__device__ __forceinline__ void gather8(const __half* __restrict__ xin,
                                        int beg, int end, int q,
                                        unsigned long long acc[4]) {
    acc[0] = acc[1] = acc[2] = acc[3] = 0ull;
    int k = beg;
    for (; k + 4 <= end; k += 4) {
        float4 ea = *(const float4*)(g_edge + k);        // edges k, k+1
        float4 eb = *(const float4*)(g_edge + k + 2);    // edges k+2, k+3
        uint4 v0 = *((const uint4*)(xin + __float_as_int(ea.x) * Cc) + q);
        uint4 v1 = *((const uint4*)(xin + __float_as_int(ea.z) * Cc) + q);
        uint4 v2 = *((const uint4*)(xin + __float_as_int(eb.x) * Cc) + q);
        uint4 v3 = *((const uint4*)(xin + __float_as_int(eb.z) * Cc) + q);
        acc8(v0, ea.y, acc);
        acc8(v1, ea.w, acc);
        acc8(v2, eb.y, acc);
        acc8(v3, eb.w, acc);
    }
    for (; k < end; k++) {
        float2 e = g_edge[k];
        uint4 v = *((const uint4*)(xin + __float_as_int(e.x) * Cc) + q);
        acc8(v, e.y, acc);
    }
}

__device__ __forceinline__ void unpack2(unsigned long long a, float& lo, float& hi) {
    asm("mov.b64 {%0, %1}, %2;" : "=f"(lo), "=f"(hi) : "l"(a));
}

// round 1: y1[t] = dinv[t]^2 * sum w*y0[src]   (half out). 4 nodes / block.
__global__ __launch_bounds__(128) void k_prop1() {
    int t = blockIdx.x * 4 + (threadIdx.x >> 5);
    int q = threadIdx.x & 31;
    int beg = t * CAP, end = beg + min(g_cnt[t], CAP);
    unsigned long long acc[4];
    gather8(g_xh, beg, end, q, acc);
    float dv = g_dinv[t];
    float s = dv * dv;
    float l0, h0, l1, h1, l2, h2, l3, h3;
    unpack2(acc[0], l0, h0); unpack2(acc[1], l1, h1);
    unpack2(acc[2], l2, h2); unpack2(acc[3], l3, h3);
    uint4 o;
    *(__half2*)&o.x = __floats2half2_rn(l0 * s, h0 * s);
    *(__half2*)&o.y = __floats2half2_rn(l1 * s, h1 * s);
    *(__half2*)&o.z = __floats2half2_rn(l2 * s, h2 * s);
    *(__half2*)&o.w = __floats2half2_rn(l3 * s, h3 * s);
    *((uint4*)(g_xbh + t * Cc) + q) = o;
}

// round 2: h2[t] = dinv[t] * sum w*y1[src]   (fp32 out). 4 nodes / block.
__global__ __launch_bounds__(128) void k_prop2() {
    int t = blockIdx.x * 4 + (threadIdx.x >> 5);
    int q = threadIdx.x & 31;
    int beg = t * CAP, end = beg + min(g_cnt[t], CAP);
    unsigned long long acc[4];
    gather8(g_xbh, beg, end, q, acc);
    float dv = g_dinv[t];
    float l0, h0, l1, h1, l2, h2, l3, h3;
    unpack2(acc[0], l0, h0); unpack2(acc[1], l1, h1);
    unpack2(acc[2], l2, h2); unpack2(acc[3], l3, h3);
    float4* outp = (float4*)(g_xa + t * Cc) + 2 * q;
    outp[0] = make_float4(l0 * dv, h0 * dv, l1 * dv, h1 * dv);
    outp[1] = make_float4(l2 * dv, h2 * dv, l3 * dv, h3 * dv);
}

// ---------------- tf32 tensor-core GEMM ----------------------------------
__device__ __forceinline__ uint32_t f2tf32(float f) {
    uint32_t u;
    asm("cvt.rna.tf32.f32 %0, %1;" : "=r"(u) : "f"(f));
    return u;
}
#define SWZ(m, k) (((m) << 5) + ((k) ^ (((m) & 7) << 2)))

__global__ __launch_bounds__(256) void k_gemm_tc(const float* __restrict__ W,
                                                 const float* __restrict__ bias,
                                                 float* __restrict__ out) {
    __shared__ uint32_t As[128 * 32];
    __shared__ uint32_t Bs[64 * 32];
    int tid = threadIdx.x;
    int warp = tid >> 5, lane = tid & 31;
    int g = lane >> 2, t4 = lane & 3;
    int warpM = warp & 3, warpN = warp >> 2;
    int row0 = blockIdx.y * 128, col0 = blockIdx.x * 64;

    float acc[2][4][4];
    #pragma unroll
    for (int i = 0; i < 2; i++)
        #pragma unroll
        for (int j = 0; j < 4; j++)
            #pragma unroll
            for (int r = 0; r < 4; r++) acc[i][j][r] = 0.f;

    for (int k0 = 0; k0 < Cc; k0 += 32) {
        #pragma unroll
        for (int i = tid; i < 128 * 8; i += 256) {
            int m = i >> 3, q = i & 7;
            int r = row0 + m;
            float4 v = make_float4(0.f, 0.f, 0.f, 0.f);
            if (r < Nn) v = *(const float4*)(g_xa + r * Cc + k0 + q * 4);
            uint32_t* dst = &As[SWZ(m, q * 4)];
            dst[0] = f2tf32(v.x); dst[1] = f2tf32(v.y);
            dst[2] = f2tf32(v.z); dst[3] = f2tf32(v.w);
        }
        #pragma unroll
        for (int i = tid; i < 64 * 8; i += 256) {
            int n = i >> 3, q = i & 7;
            float4 v = *(const float4*)(W + (col0 + n) * Cc + k0 + q * 4);
            uint32_t* dst = &Bs[SWZ(n, q * 4)];
            dst[0] = f2tf32(v.x); dst[1] = f2tf32(v.y);
            dst[2] = f2tf32(v.z); dst[3] = f2tf32(v.w);
        }
        __syncthreads();

        #pragma unroll
        for (int ks = 0; ks < 4; ks++) {
            int kb = ks * 8;
            uint32_t bf[4][2];
            #pragma unroll
            for (int nt = 0; nt < 4; nt++) {
                int n = warpN * 32 + nt * 8 + g;
                bf[nt][0] = Bs[SWZ(n, kb + t4)];
                bf[nt][1] = Bs[SWZ(n, kb + t4 + 4)];
            }
            #pragma unroll
            for (int mt = 0; mt < 2; mt++) {
                int m = warpM * 32 + mt * 16;
                uint32_t a0 = As[SWZ(m + g,     kb + t4)];
                uint32_t a1 = As[SWZ(m + g + 8, kb + t4)];
                uint32_t a2 = As[SWZ(m + g,     kb + t4 + 4)];
                uint32_t a3 = As[SWZ(m + g + 8, kb + t4 + 4)];
                #pragma unroll
                for (int nt = 0; nt < 4; nt++) {
                    asm volatile(
                        "mma.sync.aligned.m16n8k8.row.col.f32.tf32.tf32.f32 "
                        "{%0,%1,%2,%3}, {%4,%5,%6,%7}, {%8,%9}, {%0,%1,%2,%3};"
                        : "+f"(acc[mt][nt][0]), "+f"(acc[mt][nt][1]),
                          "+f"(acc[mt][nt][2]), "+f"(acc[mt][nt][3])
                        : "r"(a0), "r"(a1), "r"(a2), "r"(a3),
                          "r"(bf[nt][0]), "r"(bf[nt][1]));
                }
            }
        }
        __syncthreads();
    }

    #pragma unroll
    for (int mt = 0; mt < 2; mt++) {
        int r0 = row0 + warpM * 32 + mt * 16 + g;
        #pragma unroll
        for (int nt = 0; nt < 4; nt++) {
            int o = col0 + warpN * 32 + nt * 8 + 2 * t4;
            float b0 = bias[o], b1 = bias[o + 1];
            if (r0 < Nn) {
                out[r0 * Cc + o]     = acc[mt][nt][0] + b0;
                out[r0 * Cc + o + 1] = acc[mt][nt][1] + b1;
            }
            if (r0 + 8 < Nn) {
                out[(r0 + 8) * Cc + o]     = acc[mt][nt][2] + b0;
                out[(r0 + 8) * Cc + o + 1] = acc[mt][nt][3] + b1;
            }
        }
    }
}

// ---------------- launch ----------------
extern "C" void kernel_launch(void* const* d_in, const int* in_sizes, int n_in,
                              void* d_out, int out_size) {
    const float* x  = (const float*)d_in[0];
    const void*  ei = d_in[1];
    const float* w  = (const float*)d_in[2];
    const float* lw = (const float*)d_in[3];
    const float* lb = (const float*)d_in[4];
    float* out = (float*)d_out;

    k_init<<<(Nn + 255) / 256, 256>>>(ei);
    k_edges<<<(Ee + 255) / 256, 256>>>(ei, w);
    k_normalize<<<Nn, 256>>>(x);
    k_prop1<<<Nn / 4, 128>>>();
    k_prop2<<<Nn / 4, 128>>>();
    dim3 ggrid(Cc / 64, (Nn + 127) / 128);
    k_gemm_tc<<<ggrid, 256>>>(lw, lb, out);
}

// round 13
// speedup vs baseline: 1.0745x; 1.0745x over previous
#include <cuda_runtime.h>
#include <cuda_fp16.h>
#include <cstdint>

#define Nn 20000
#define Ee 640000
#define Cc 256
#define CAP 160              // bucket capacity per node (deg ~ Poisson(32))

// ---------------- device scratch (no allocations allowed) ----------------
__device__ __half  g_xh [Nn * Cc];    // y0 = dinv*x_norm, half (round-1 gather input)
__device__ __half  g_xbh[Nn * Cc];    // y1 = dinv^2 * S1, half (round-2 gather input)
__device__ __half  g_xah[Nn * Cc];    // h2 = dinv * S2, half (GEMM A input)
__device__ float   g_dinv[Nn];
__device__ int     g_cnt[Nn];
__device__ float2  g_edge[Nn * CAP];  // bucket CSR: .x = src (bit-cast), .y = raw weight
__device__ int     g_is64;

__device__ __forceinline__ int edge_at(const void* p, long long idx) {
    int v;
    if (g_is64) v = (int)((const long long*)p)[idx];
    else        v = ((const int*)p)[idx];
    return (v < 0) ? 0 : (v >= Nn ? Nn - 1 : v);
}

// ---------------- setup kernels ----------------

__global__ void k_init(const void* ei) {
    int i = blockIdx.x * blockDim.x + threadIdx.x;
    if (i < Nn) g_cnt[i] = 0;
    if (blockIdx.x == 0 && threadIdx.x < 32) {
        const int* p = (const int*)ei;
        int lane = threadIdx.x;
        int nz = 0;
        #pragma unroll
        for (int j = 0; j < 8; j++)
            nz |= p[2 * (lane + 32 * j) + 1];
        unsigned any = __ballot_sync(0xffffffffu, nz != 0);
        if (lane == 0) g_is64 = (any == 0) ? 1 : 0;
    }
}

// SINGLE edge pass: bucket scatter of (src, raw w); cnt atomic only
__global__ void k_edges(const void* __restrict__ ei, const float* __restrict__ w) {
    int e = blockIdx.x * blockDim.x + threadIdx.x;
    if (e < Ee) {
        int r = edge_at(ei, e);
        int c = edge_at(ei, (long long)Ee + e);
        int p = atomicAdd(&g_cnt[c], 1);
        if (p < CAP) g_edge[c * CAP + p] = make_float2(__int_as_float(r), w[e]);
    }
}

// L2-normalize row n of x, deg[n] from bucket weights, scale by dinv, half out
__global__ void k_normalize(const float* __restrict__ x) {
    int n = blockIdx.x;
    int c = threadIdx.x;
    float v = x[n * Cc + c];
    float sq = v * v;
    int cnt = min(g_cnt[n], CAP);
    float wsum = 0.f;
    for (int i = c; i < cnt; i += 256) wsum += g_edge[n * CAP + i].y;
    #pragma unroll
    for (int o = 16; o > 0; o >>= 1) {
        sq   += __shfl_xor_sync(0xffffffffu, sq,   o);
        wsum += __shfl_xor_sync(0xffffffffu, wsum, o);
    }
    __shared__ float ws[8], wd[8];
    __shared__ float s_scale;
    if ((c & 31) == 0) { ws[c >> 5] = sq; wd[c >> 5] = wsum; }
    __syncthreads();
    if (c == 0) {
        float s = 0.f, d = 0.f;
        #pragma unroll
        for (int i = 0; i < 8; i++) { s += ws[i]; d += wd[i]; }
        float dinv = (d > 0.f) ? rsqrtf(d) : 0.f;
        g_dinv[n] = dinv;
        s_scale = dinv / fmaxf(sqrtf(s), 1e-12f);
    }
    __syncthreads();
    g_xh[n * Cc + c] = __float2half_rn(v * s_scale);
}

// ---------------- propagation (R10 shape): 64 thr/node, uint2 loads ------
struct Acc4 { float a0, a1, a2, a3; };

__device__ __forceinline__ void gather_node(const __half* __restrict__ xin,
                                            int beg, int end, int q, Acc4& acc) {
    acc.a0 = acc.a1 = acc.a2 = acc.a3 = 0.f;
    int k = beg;
    for (; k + 4 <= end; k += 4) {
        float2 e0 = g_edge[k],     e1 = g_edge[k + 1];
        float2 e2 = g_edge[k + 2], e3 = g_edge[k + 3];
        uint2 v0 = *((const uint2*)(xin + __float_as_int(e0.x) * Cc) + q);
        uint2 v1 = *((const uint2*)(xin + __float_as_int(e1.x) * Cc) + q);
        uint2 v2 = *((const uint2*)(xin + __float_as_int(e2.x) * Cc) + q);
        uint2 v3 = *((const uint2*)(xin + __float_as_int(e3.x) * Cc) + q);
        float2 p;
        p = __half22float2(*(__half2*)&v0.x); acc.a0 += e0.y * p.x; acc.a1 += e0.y * p.y;
        p = __half22float2(*(__half2*)&v0.y); acc.a2 += e0.y * p.x; acc.a3 += e0.y * p.y;
        p = __half22float2(*(__half2*)&v1.x); acc.a0 += e1.y * p.x; acc.a1 += e1.y * p.y;
        p = __half22float2(*(__half2*)&v1.y); acc.a2 += e1.y * p.x; acc.a3 += e1.y * p.y;
        p = __half22float2(*(__half2*)&v2.x); acc.a0 += e2.y * p.x; acc.a1 += e2.y * p.y;
        p = __half22float2(*(__half2*)&v2.y); acc.a2 += e2.y * p.x; acc.a3 += e2.y * p.y;
        p = __half22float2(*(__half2*)&v3.x); acc.a0 += e3.y * p.x; acc.a1 += e3.y * p.y;
        p = __half22float2(*(__half2*)&v3.y); acc.a2 += e3.y * p.x; acc.a3 += e3.y * p.y;
    }
    for (; k < end; k++) {
        float2 e0 = g_edge[k];
        uint2 v0 = *((const uint2*)(xin + __float_as_int(e0.x) * Cc) + q);
        float2 p;
        p = __half22float2(*(__half2*)&v0.x); acc.a0 += e0.y * p.x; acc.a1 += e0.y * p.y;
        p = __half22float2(*(__half2*)&v0.y); acc.a2 += e0.y * p.x; acc.a3 += e0.y * p.y;
    }
}

// round 1: y1[t] = dinv[t]^2 * sum w*y0[src]   (half out)
__global__ void k_prop1() {
    int t = blockIdx.x, q = threadIdx.x;
    int beg = t * CAP, end = beg + min(g_cnt[t], CAP);
    Acc4 acc;
    gather_node(g_xh, beg, end, q, acc);
    float dv = g_dinv[t];
    float s = dv * dv;
    uint2 o;
    *(__half2*)&o.x = __floats2half2_rn(acc.a0 * s, acc.a1 * s);
    *(__half2*)&o.y = __floats2half2_rn(acc.a2 * s, acc.a3 * s);
    *((uint2*)(g_xbh + t * Cc) + q) = o;
}

// round 2: h2[t] = dinv[t] * sum w*y1[src]   (half out now)
__global__ void k_prop2() {
    int t = blockIdx.x, q = threadIdx.x;
    int beg = t * CAP, end = beg + min(g_cnt[t], CAP);
    Acc4 acc;
    gather_node(g_xbh, beg, end, q, acc);
    float dv = g_dinv[t];
    uint2 o;
    *(__half2*)&o.x = __floats2half2_rn(acc.a0 * dv, acc.a1 * dv);
    *(__half2*)&o.y = __floats2half2_rn(acc.a2 * dv, acc.a3 * dv);
    *((uint2*)(g_xah + t * Cc) + q) = o;
}

// ---------------- fp16 tensor-core GEMM (m16n8k16, fp32 accum) -----------
// out[n][o] = sum_c h2[n][c] * W[o][c] + bias[o]
// BM=128 BN=64 BK=32 halves. SMEM rows padded to 20 words (conflict-free:
// banks (20*g mod 32)+t are all-distinct over the fragment access pattern).
#define AW 20
__global__ __launch_bounds__(256) void k_gemm_hmma(const float* __restrict__ W,
                                                   const float* __restrict__ bias,
                                                   float* __restrict__ out) {
    __shared__ uint32_t As[128 * AW];   // 128 rows x 16 data words (+4 pad)
    __shared__ uint32_t Bs[64 * AW];
    int tid = threadIdx.x;
    int warp = tid >> 5, lane = tid & 31;
    int g = lane >> 2, t4 = lane & 3;
    int warpM = warp & 3, warpN = warp >> 2;          // 4 x 2 warps, 32x32 tiles
    int row0 = blockIdx.y * 128, col0 = blockIdx.x * 64;

    float acc[2][4][4];
    #pragma unroll
    for (int i = 0; i < 2; i++)
        #pragma unroll
        for (int j = 0; j < 4; j++)
            #pragma unroll
            for (int r = 0; r < 4; r++) acc[i][j][r] = 0.f;

    for (int k0 = 0; k0 < Cc; k0 += 32) {
        // fill A: 128 rows x 16 words; 2 threads/row, 8 words each (2 x uint4)
        {
            int m = tid >> 1, h = tid & 1;
            int r = row0 + m;
            uint4 va = make_uint4(0, 0, 0, 0), vb = make_uint4(0, 0, 0, 0);
            if (r < Nn) {
                const uint4* src = (const uint4*)(g_xah + r * Cc + k0 + h * 16);
                va = src[0];                 // halves h*16 .. h*16+7
                vb = src[1];                 // halves h*16+8 .. h*16+15
            }
            uint32_t* dst = &As[m * AW + h * 8];
            dst[0] = va.x; dst[1] = va.y; dst[2] = va.z; dst[3] = va.w;
            dst[4] = vb.x; dst[5] = vb.y; dst[6] = vb.z; dst[7] = vb.w;
        }
        // fill B: 64 rows x 16 words; 4 threads/row, 4 words (8 floats) each
        {
            int n = tid >> 2, p = tid & 3;
            const float4* src = (const float4*)(W + (col0 + n) * Cc + k0 + p * 8);
            float4 f0 = src[0], f1 = src[1];
            uint32_t* dst = &Bs[n * AW + p * 4];
            *(__half2*)&dst[0] = __floats2half2_rn(f0.x, f0.y);
            *(__half2*)&dst[1] = __floats2half2_rn(f0.z, f0.w);
            *(__half2*)&dst[2] = __floats2half2_rn(f1.x, f1.y);
            *(__half2*)&dst[3] = __floats2half2_rn(f1.z, f1.w);
        }
        __syncthreads();

        #pragma unroll
        for (int s = 0; s < 2; s++) {       // two k16 steps per 32-half tile
            int kb = s * 8;
            uint32_t bf[4][2];
            #pragma unroll
            for (int nt = 0; nt < 4; nt++) {
                int n = warpN * 32 + nt * 8 + g;
                bf[nt][0] = Bs[n * AW + kb + t4];
                bf[nt][1] = Bs[n * AW + kb + t4 + 4];
            }
            #pragma unroll
            for (int mt = 0; mt < 2; mt++) {
                int m = warpM * 32 + mt * 16;
                uint32_t a0 = As[(m + g)     * AW + kb + t4];
                uint32_t a1 = As[(m + g + 8) * AW + kb + t4];
                uint32_t a2 = As[(m + g)     * AW + kb + t4 + 4];
                uint32_t a3 = As[(m + g + 8) * AW + kb + t4 + 4];
                #pragma unroll
                for (int nt = 0; nt < 4; nt++) {
                    asm volatile(
                        "mma.sync.aligned.m16n8k16.row.col.f32.f16.f16.f32 "
                        "{%0,%1,%2,%3}, {%4,%5,%6,%7}, {%8,%9}, {%0,%1,%2,%3};"
                        : "+f"(acc[mt][nt][0]), "+f"(acc[mt][nt][1]),
                          "+f"(acc[mt][nt][2]), "+f"(acc[mt][nt][3])
                        : "r"(a0), "r"(a1), "r"(a2), "r"(a3),
                          "r"(bf[nt][0]), "r"(bf[nt][1]));
                }
            }
        }
        __syncthreads();
    }

    #pragma unroll
    for (int mt = 0; mt < 2; mt++) {
        int r0 = row0 + warpM * 32 + mt * 16 + g;
        #pragma unroll
        for (int nt = 0; nt < 4; nt++) {
            int o = col0 + warpN * 32 + nt * 8 + 2 * t4;
            float b0 = bias[o], b1 = bias[o + 1];
            if (r0 < Nn) {
                out[r0 * Cc + o]     = acc[mt][nt][0] + b0;
                out[r0 * Cc + o + 1] = acc[mt][nt][1] + b1;
            }
            if (r0 + 8 < Nn) {
                out[(r0 + 8) * Cc + o]     = acc[mt][nt][2] + b0;
                out[(r0 + 8) * Cc + o + 1] = acc[mt][nt][3] + b1;
            }
        }
    }
}

// ---------------- launch ----------------
extern "C" void kernel_launch(void* const* d_in, const int* in_sizes, int n_in,
                              void* d_out, int out_size) {
    const float* x  = (const float*)d_in[0];
    const void*  ei = d_in[1];
    const float* w  = (const float*)d_in[2];
    const float* lw = (const float*)d_in[3];
    const float* lb = (const float*)d_in[4];
    float* out = (float*)d_out;

    k_init<<<(Nn + 255) / 256, 256>>>(ei);
    k_edges<<<(Ee + 255) / 256, 256>>>(ei, w);
    k_normalize<<<Nn, 256>>>(x);
    k_prop1<<<Nn, 64>>>();
    k_prop2<<<Nn, 64>>>();
    dim3 ggrid(Cc / 64, (Nn + 127) / 128);
    k_gemm_hmma<<<ggrid, 256>>>(lw, lb, out);
}